// round 1
// baseline (speedup 1.0000x reference)
#include <cuda_runtime.h>

#define D        128
#define RSTRIDE  132          // padded row stride (floats) -> conflict-free LDS
#define MAXB     16384
#define MAXREL   256
#define CHUNKS   8

// ---- scratch (no allocation allowed) ----
__device__ int g_counts[MAXREL];
__device__ int g_offsets[MAXREL + 1];
__device__ int g_cursor[MAXREL];
__device__ int g_sorted[MAXB];

// ---------------- counting sort by relation ----------------
__global__ void k_zero(int nrel) {
    int i = blockIdx.x * blockDim.x + threadIdx.x;
    if (i < nrel) g_counts[i] = 0;
}

__global__ void k_hist(const int* __restrict__ rel, int B) {
    int i = blockIdx.x * blockDim.x + threadIdx.x;
    if (i < B) atomicAdd(&g_counts[rel[i]], 1);
}

__global__ void k_scan(int nrel) {
    if (threadIdx.x == 0 && blockIdx.x == 0) {
        int acc = 0;
        for (int r = 0; r < nrel; r++) {
            g_offsets[r] = acc;
            g_cursor[r]  = acc;
            acc += g_counts[r];
        }
        g_offsets[nrel] = acc;
    }
}

__global__ void k_scatter(const int* __restrict__ rel, int B) {
    int i = blockIdx.x * blockDim.x + threadIdx.x;
    if (i < B) {
        int p = atomicAdd(&g_cursor[rel[i]], 1);
        g_sorted[p] = i;   // bucket order nondeterministic, but per-sample score is
                           // computed identically regardless of slot -> output deterministic
    }
}

// ---------------- main compute ----------------
// block = 128 threads, one block per (relation, chunk).
// SMEM: R (128x132 fp32, padded) + double-buffered t/nt vectors + reduce scratch.
extern "C" __global__ void __launch_bounds__(128, 3)
k_compute(const int*   __restrict__ heads,
          const int*   __restrict__ tails,
          const int*   __restrict__ nheads,
          const int*   __restrict__ ntails,
          const float* __restrict__ ent,
          const float* __restrict__ relm,
          float*       __restrict__ out,
          int B)
{
    extern __shared__ float smem[];
    float* Rs  = smem;                       // D * RSTRIDE
    float* ts  = Rs  + D * RSTRIDE;          // 2 * D
    float* nts = ts  + 2 * D;                // 2 * D
    float* red = nts + 2 * D;                // 8

    const int rel   = blockIdx.x / CHUNKS;
    const int chunk = blockIdx.x % CHUNKS;

    const int beg    = g_offsets[rel];
    const int endAll = g_offsets[rel + 1];
    const int n      = endAll - beg;
    const int per    = (n + CHUNKS - 1) / CHUNKS;
    const int start  = beg + chunk * per;
    const int end    = min(start + per, endAll);
    if (start >= end) return;                // uniform across block

    const int d    = threadIdx.x;
    const int warp = d >> 5;
    const int lane = d & 31;

    // ---- load R[rel] into padded SMEM (coalesced float4) ----
    const float4* Rg = (const float4*)(relm + (size_t)rel * D * D);
#pragma unroll
    for (int k = 0; k < 32; k++) {
        int idx4 = d + k * 128;              // 0..4095 float4s
        float4 v = Rg[idx4];
        int row = idx4 >> 5;                 // (idx4*4)/128
        int col = (idx4 & 31) << 2;
        *(float4*)&Rs[row * RSTRIDE + col] = v;
    }

    // ---- prefetch sample 0 ----
    int s     = start;
    int cur_i = g_sorted[s];
    float h_r  = ent[(size_t)heads [cur_i] * D + d];
    float t_r  = ent[(size_t)tails [cur_i] * D + d];
    float nh_r = ent[(size_t)nheads[cur_i] * D + d];
    float nt_r = ent[(size_t)ntails[cur_i] * D + d];

    int buf = 0;
    for (; s < end; ++s) {
        ts [buf * D + d] = t_r;
        nts[buf * D + d] = nt_r;
        const float hc  = h_r;
        const float nhc = nh_r;
        const int   out_i = cur_i;

        __syncthreads();   // t/nt visible; also orders R-load before first compute

        // prefetch next sample while computing (hide DRAM latency)
        if (s + 1 < end) {
            int ni = g_sorted[s + 1];
            cur_i = ni;
            h_r  = ent[(size_t)heads [ni] * D + d];
            t_r  = ent[(size_t)tails [ni] * D + d];
            nh_r = ent[(size_t)nheads[ni] * D + d];
            nt_r = ent[(size_t)ntails[ni] * D + d];
        }

        const float* trow  = ts  + buf * D;
        const float* ntrow = nts + buf * D;
        const float* rrow  = Rs + d * RSTRIDE;

        float a0 = 0.f, a1 = 0.f, b0 = 0.f, b1 = 0.f;
#pragma unroll
        for (int k = 0; k < 32; k++) {
            float4 r4 = *(const float4*)(rrow  + 4 * k);
            float4 t4 = *(const float4*)(trow  + 4 * k);
            float4 n4 = *(const float4*)(ntrow + 4 * k);
            a0 = fmaf(r4.x, t4.x, a0); a1 = fmaf(r4.y, t4.y, a1);
            a0 = fmaf(r4.z, t4.z, a0); a1 = fmaf(r4.w, t4.w, a1);
            b0 = fmaf(r4.x, n4.x, b0); b1 = fmaf(r4.y, n4.y, b1);
            b0 = fmaf(r4.z, n4.z, b0); b1 = fmaf(r4.w, n4.w, b1);
        }
        float ppos = hc  * (a0 + a1);
        float pneg = nhc * (b0 + b1);

#pragma unroll
        for (int off = 16; off; off >>= 1) {
            ppos += __shfl_xor_sync(0xffffffffu, ppos, off);
            pneg += __shfl_xor_sync(0xffffffffu, pneg, off);
        }
        if (lane == 0) { red[warp] = ppos; red[4 + warp] = pneg; }
        __syncthreads();
        if (d == 0) {
            out[out_i]     = red[0] + red[1] + red[2] + red[3];
            out[B + out_i] = red[4] + red[5] + red[6] + red[7];
        }
        buf ^= 1;
    }
}

// ---------------- launch ----------------
extern "C" void kernel_launch(void* const* d_in, const int* in_sizes, int n_in,
                              void* d_out, int out_size)
{
    const int*   heads  = (const int*)  d_in[0];
    const int*   tails  = (const int*)  d_in[1];
    const int*   nheads = (const int*)  d_in[2];
    const int*   ntails = (const int*)  d_in[3];
    const int*   rels   = (const int*)  d_in[4];
    const float* ent    = (const float*)d_in[5];
    const float* relm   = (const float*)d_in[6];
    float*       out    = (float*)      d_out;

    const int B    = in_sizes[0];
    const int nrel = in_sizes[6] / (D * D);

    k_zero   <<<(nrel + 255) / 256, 256>>>(nrel);
    k_hist   <<<(B    + 255) / 256, 256>>>(rels, B);
    k_scan   <<<1, 32>>>(nrel);
    k_scatter<<<(B    + 255) / 256, 256>>>(rels, B);

    const size_t smem_bytes = (D * RSTRIDE + 4 * D + 8) * sizeof(float); // ~69.7 KB
    cudaFuncSetAttribute(k_compute, cudaFuncAttributeMaxDynamicSharedMemorySize,
                         (int)smem_bytes);
    k_compute<<<nrel * CHUNKS, 128, smem_bytes>>>(heads, tails, nheads, ntails,
                                                  ent, relm, out, B);
}

// round 2
// speedup vs baseline: 1.2456x; 1.2456x over previous
#include <cuda_runtime.h>
#include <cstdint>

#define D        128
#define MAXB     16384
#define MAXREL   256
#define CHUNKS   4
#define G        8       // samples per batch
#define GT       4       // g-tile per thread
#define NTH      256

// ---- scratch (no allocation allowed) ----
__device__ int g_counts[MAXREL];
__device__ int g_offsets[MAXREL + 1];
__device__ int g_cursor[MAXREL];
__device__ int g_sorted[MAXB];

// ============ prep: counting sort by relation ============
__global__ void k_zero(int nrel) {
    int i = blockIdx.x * blockDim.x + threadIdx.x;
    if (i < nrel) g_counts[i] = 0;
}

__global__ void k_hist(const int* __restrict__ rel, int B, int nrel) {
    __shared__ int sh[MAXREL];
    for (int i = threadIdx.x; i < nrel; i += blockDim.x) sh[i] = 0;
    __syncthreads();
    for (int i = blockIdx.x * blockDim.x + threadIdx.x; i < B;
         i += gridDim.x * blockDim.x)
        atomicAdd(&sh[rel[i]], 1);
    __syncthreads();
    for (int i = threadIdx.x; i < nrel; i += blockDim.x) {
        int c = sh[i];
        if (c) atomicAdd(&g_counts[i], c);
    }
}

// 1 block, 256 threads; nrel <= 255
__global__ void k_scan(int nrel) {
    __shared__ int wsum[8];
    int t = threadIdx.x, lane = t & 31, w = t >> 5;
    int v = (t < nrel) ? g_counts[t] : 0;
    int x = v;
#pragma unroll
    for (int o = 1; o < 32; o <<= 1) {
        int y = __shfl_up_sync(0xffffffffu, x, o);
        if (lane >= o) x += y;
    }
    if (lane == 31) wsum[w] = x;
    __syncthreads();
    if (w == 0) {
        int s = (lane < 8) ? wsum[lane] : 0;
#pragma unroll
        for (int o = 1; o < 8; o <<= 1) {
            int y = __shfl_up_sync(0xffffffffu, s, o);
            if (lane >= o) s += y;
        }
        if (lane < 8) wsum[lane] = s;
    }
    __syncthreads();
    int excl = x - v + ((w > 0) ? wsum[w - 1] : 0);
    if (t < nrel) { g_offsets[t] = excl; g_cursor[t] = excl; }
    if (t == nrel) g_offsets[t] = excl;
}

// block-aggregated scatter: smem local ranks, one global reserve per (block,rel)
__global__ void k_scatter(const int* __restrict__ rel, int B, int nrel) {
    __shared__ int bc[MAXREL];
    __shared__ int base[MAXREL];
    int tid = threadIdx.x;
    for (int i = tid; i < nrel; i += blockDim.x) bc[i] = 0;
    __syncthreads();
    int i = blockIdx.x * blockDim.x + tid;
    int r = 0, lr = 0;
    if (i < B) { r = rel[i]; lr = atomicAdd(&bc[r], 1); }
    __syncthreads();
    for (int j = tid; j < nrel; j += blockDim.x) {
        int c = bc[j];
        base[j] = c ? atomicAdd(&g_cursor[j], c) : 0;
    }
    __syncthreads();
    if (i < B) g_sorted[base[r] + lr] = i;
}

// ============ cp.async helpers ============
__device__ __forceinline__ void cpa16(void* dst, const void* src) {
    uint32_t d32 = (uint32_t)__cvta_generic_to_shared(dst);
    asm volatile("cp.async.cg.shared.global [%0], [%1], 16;\n"
                 :: "r"(d32), "l"(src) : "memory");
}
__device__ __forceinline__ void cpa_commit() {
    asm volatile("cp.async.commit_group;\n" ::: "memory");
}
template <int N>
__device__ __forceinline__ void cpa_wait() {
    asm volatile("cp.async.wait_group %0;\n" :: "n"(N) : "memory");
}

// ============ main compute ============
// One block per (relation, chunk). 256 threads.
// Thread (lane, w): wsub=w&3, gset=w>>2 -> d = lane+32*wsub, g0 = gset*GT.
// R stored swizzled: float4 of row rd, cols [4e4..4e4+3] at slot e4*128 + (rd^e4).
extern "C" __global__ void __launch_bounds__(NTH, 2)
k_compute(const int*   __restrict__ heads,
          const int*   __restrict__ tails,
          const int*   __restrict__ nheads,
          const int*   __restrict__ ntails,
          const float* __restrict__ ent,
          const float* __restrict__ relm,
          float*       __restrict__ out,
          int B)
{
    extern __shared__ float sm[];
    float* Rs   = sm;                         // D*D swizzled
    float* Vb   = Rs + D * D;                 // [2 buf][4 vec][G][D]
    float* sc   = Vb + 2 * 4 * G * D;         // [2][G]  pos,neg scores
    int*   sidx = (int*)(sc + 2 * G);         // [2 buf][G]

    const int rel    = blockIdx.x / CHUNKS;
    const int chunk  = blockIdx.x % CHUNKS;
    const int beg    = g_offsets[rel];
    const int endAll = g_offsets[rel + 1];
    const int n      = endAll - beg;
    const int per    = (n + CHUNKS - 1) / CHUNKS;
    const int start  = beg + chunk * per;
    const int end    = min(start + per, endAll);
    if (start >= end) return;                 // uniform across block
    const int nb = (end - start + G - 1) / G;

    const int tid  = threadIdx.x;
    const int lane = tid & 31;
    const int w    = tid >> 5;
    const int wsub = w & 3;
    const int d    = lane + 32 * wsub;
    const int g0   = (w >> 2) * GT;

    // ---- stage R (swizzled) via cp.async ----
    const float* Rg = relm + (size_t)rel * D * D;
#pragma unroll
    for (int k = 0; k < 16; k++) {
        int idx4 = tid + k * NTH;            // 0..4095 float4s
        int rd = idx4 >> 5, e4 = idx4 & 31;
        int slot = e4 * 128 + (rd ^ e4);
        cpa16(Rs + 4 * slot, Rg + 4 * idx4);
    }

    // ---- gather one batch (4 cp.async / thread) ----
    auto gather = [&](int b) {
        int buf = b & 1;
        if (tid < G)
            sidx[buf * G + tid] = g_sorted[min(start + b * G + tid, end - 1)];
#pragma unroll
        for (int k = 0; k < 4; k++) {
            int q    = tid + k * NTH;        // 0..1023
            int col  = q & 31;
            int slot = q >> 5;               // 0..31
            int v    = slot & 3;
            int g    = slot >> 2;
            int s    = min(start + b * G + g, end - 1);
            int i    = g_sorted[s];
            const int* arr = (v == 0) ? heads : (v == 1) ? tails
                           : (v == 2) ? nheads : ntails;
            int row = arr[i];
            cpa16(Vb + ((size_t)(buf * 4 + v) * G + g) * D + col * 4,
                  ent + (size_t)row * D + col * 4);
        }
    };

    gather(0);
    cpa_commit();                             // group: R + batch0
    if (nb > 1) { gather(1); }
    cpa_commit();                             // group: batch1 (possibly empty)

    if (tid < 2 * G) sc[tid] = 0.0f;          // zero scores once

    for (int b = 0; b < nb; b++) {
        const int buf = b & 1;
        if (b + 1 < nb) cpa_wait<1>(); else cpa_wait<0>();
        __syncthreads();                      // buffer b ready (and sc zeroed)

        const float* Hv  = Vb + (size_t)(buf * 4 + 0) * G * D;
        const float* Tv  = Vb + (size_t)(buf * 4 + 1) * G * D;
        const float* NHv = Vb + (size_t)(buf * 4 + 2) * G * D;
        const float* NTv = Vb + (size_t)(buf * 4 + 3) * G * D;

        float a0 = 0.f, a1 = 0.f, a2 = 0.f, a3 = 0.f;
        float b0 = 0.f, b1 = 0.f, b2 = 0.f, b3 = 0.f;

#pragma unroll 4
        for (int e4 = 0; e4 < 32; e4++) {
            float4 r = *(const float4*)(Rs + 4 * (e4 * 128 + (d ^ e4)));
            {
                float4 t = *(const float4*)(Tv + (size_t)(g0 + 0) * D + 4 * e4);
                a0 = fmaf(r.x, t.x, a0); a0 = fmaf(r.y, t.y, a0);
                a0 = fmaf(r.z, t.z, a0); a0 = fmaf(r.w, t.w, a0);
            }
            {
                float4 t = *(const float4*)(Tv + (size_t)(g0 + 1) * D + 4 * e4);
                a1 = fmaf(r.x, t.x, a1); a1 = fmaf(r.y, t.y, a1);
                a1 = fmaf(r.z, t.z, a1); a1 = fmaf(r.w, t.w, a1);
            }
            {
                float4 t = *(const float4*)(Tv + (size_t)(g0 + 2) * D + 4 * e4);
                a2 = fmaf(r.x, t.x, a2); a2 = fmaf(r.y, t.y, a2);
                a2 = fmaf(r.z, t.z, a2); a2 = fmaf(r.w, t.w, a2);
            }
            {
                float4 t = *(const float4*)(Tv + (size_t)(g0 + 3) * D + 4 * e4);
                a3 = fmaf(r.x, t.x, a3); a3 = fmaf(r.y, t.y, a3);
                a3 = fmaf(r.z, t.z, a3); a3 = fmaf(r.w, t.w, a3);
            }
            {
                float4 t = *(const float4*)(NTv + (size_t)(g0 + 0) * D + 4 * e4);
                b0 = fmaf(r.x, t.x, b0); b0 = fmaf(r.y, t.y, b0);
                b0 = fmaf(r.z, t.z, b0); b0 = fmaf(r.w, t.w, b0);
            }
            {
                float4 t = *(const float4*)(NTv + (size_t)(g0 + 1) * D + 4 * e4);
                b1 = fmaf(r.x, t.x, b1); b1 = fmaf(r.y, t.y, b1);
                b1 = fmaf(r.z, t.z, b1); b1 = fmaf(r.w, t.w, b1);
            }
            {
                float4 t = *(const float4*)(NTv + (size_t)(g0 + 2) * D + 4 * e4);
                b2 = fmaf(r.x, t.x, b2); b2 = fmaf(r.y, t.y, b2);
                b2 = fmaf(r.z, t.z, b2); b2 = fmaf(r.w, t.w, b2);
            }
            {
                float4 t = *(const float4*)(NTv + (size_t)(g0 + 3) * D + 4 * e4);
                b3 = fmaf(r.x, t.x, b3); b3 = fmaf(r.y, t.y, b3);
                b3 = fmaf(r.z, t.z, b3); b3 = fmaf(r.w, t.w, b3);
            }
        }

        // ---- epilogue: multiply by h, reduce over d ----
        float p0 = Hv[(size_t)(g0 + 0) * D + d] * a0;
        float p1 = Hv[(size_t)(g0 + 1) * D + d] * a1;
        float p2 = Hv[(size_t)(g0 + 2) * D + d] * a2;
        float p3 = Hv[(size_t)(g0 + 3) * D + d] * a3;
        float q0 = NHv[(size_t)(g0 + 0) * D + d] * b0;
        float q1 = NHv[(size_t)(g0 + 1) * D + d] * b1;
        float q2 = NHv[(size_t)(g0 + 2) * D + d] * b2;
        float q3 = NHv[(size_t)(g0 + 3) * D + d] * b3;
#pragma unroll
        for (int o = 16; o; o >>= 1) {
            p0 += __shfl_xor_sync(0xffffffffu, p0, o);
            p1 += __shfl_xor_sync(0xffffffffu, p1, o);
            p2 += __shfl_xor_sync(0xffffffffu, p2, o);
            p3 += __shfl_xor_sync(0xffffffffu, p3, o);
            q0 += __shfl_xor_sync(0xffffffffu, q0, o);
            q1 += __shfl_xor_sync(0xffffffffu, q1, o);
            q2 += __shfl_xor_sync(0xffffffffu, q2, o);
            q3 += __shfl_xor_sync(0xffffffffu, q3, o);
        }
        if (lane == 0) {
            atomicAdd(&sc[g0 + 0], p0);  atomicAdd(&sc[G + g0 + 0], q0);
            atomicAdd(&sc[g0 + 1], p1);  atomicAdd(&sc[G + g0 + 1], q1);
            atomicAdd(&sc[g0 + 2], p2);  atomicAdd(&sc[G + g0 + 2], q2);
            atomicAdd(&sc[g0 + 3], p3);  atomicAdd(&sc[G + g0 + 3], q3);
        }
        __syncthreads();                      // all partials in sc

        if (tid < G) {
            int i = sidx[buf * G + tid];
            float sp = sc[tid], sn = sc[G + tid];
            out[i]     = sp;
            out[B + i] = sn;
            sc[tid] = 0.0f; sc[G + tid] = 0.0f;   // re-zero (owned slots)
        }
        __syncthreads();                      // out/zero done, buf fully consumed

        if (b + 2 < nb) { gather(b + 2); }
        cpa_commit();
    }
}

// ============ launch ============
extern "C" void kernel_launch(void* const* d_in, const int* in_sizes, int n_in,
                              void* d_out, int out_size)
{
    const int*   heads  = (const int*)  d_in[0];
    const int*   tails  = (const int*)  d_in[1];
    const int*   nheads = (const int*)  d_in[2];
    const int*   ntails = (const int*)  d_in[3];
    const int*   rels   = (const int*)  d_in[4];
    const float* ent    = (const float*)d_in[5];
    const float* relm   = (const float*)d_in[6];
    float*       out    = (float*)      d_out;

    const int B    = in_sizes[0];
    const int nrel = in_sizes[6] / (D * D);

    k_zero<<<(nrel + 255) / 256, 256>>>(nrel);
    k_hist<<<16, 1024>>>(rels, B, nrel);
    k_scan<<<1, 256>>>(nrel);
    k_scatter<<<(B + 1023) / 1024, 1024>>>(rels, B, nrel);

    const size_t smem_bytes =
        (D * D + 2 * 4 * G * D + 2 * G) * sizeof(float) + 2 * G * sizeof(int);
    cudaFuncSetAttribute(k_compute, cudaFuncAttributeMaxDynamicSharedMemorySize,
                         (int)smem_bytes);
    k_compute<<<nrel * CHUNKS, NTH, smem_bytes>>>(heads, tails, nheads, ntails,
                                                  ent, relm, out, B);
}